// round 12
// baseline (speedup 1.0000x reference)
#include <cuda_runtime.h>
#include <cuda_bf16.h>
#include <cstdint>
#include <cstddef>

// B=32, H=W=64, C=64, K=3, S=1, PAD=1; Hp=Wp=66, OUT=192. Pure gather:
//   out[b,c2,r,s] = up_flat[c2*4356 + ip*66 + jp], ip=r/3+r%3, jp=s/3+s%3
//   up_flat[t]: p=t>>6, c=t&63, rp=p/66, cp=p%66;
//   interior -> in[b, (p-2rp-65), c] else 0.
// Stores leave the per-thread STG/L1 path: each block's output tile is
// 147456 contiguous bytes; build it in 16-row smem chunks (12288 B,
// double-buffered) and stream them out with 1D cp.async.bulk (shared->global).
#define HP          66
#define NP          (HP * HP)          // 4356
#define OUT         192
#define CHUNK_ROWS  16
#define NCHUNK      (OUT / CHUNK_ROWS)       // 12
#define CHUNK_FLTS  (CHUNK_ROWS * OUT)       // 3072
#define CHUNK_BYTES (CHUNK_FLTS * 4)         // 12288

struct __align__(16) Smem {
    float buf[2][CHUNK_FLTS];   // 2 x 12288 B
    float win[NP];              // 17424 B   (total 42000 B, fits static smem)
};

__global__ __launch_bounds__(384)
void padding_jacobians_kernel(const float* __restrict__ in,
                              float* __restrict__ out) {
    __shared__ Smem smem;

    const unsigned c2 = blockIdx.x;        // 0..63
    const unsigned b  = blockIdx.y;        // 0..31
    const int tx  = threadIdx.x;           // 0..47 (output quad)
    const int ty  = threadIdx.y;           // 0..7
    const int tid = ty * 48 + tx;

    const float* __restrict__ inb = in + (size_t)b * (64 * 64 * 64);
    const unsigned base_t = c2 * NP;       // multiple of 4

    // ---- Load phase: win[i] = up_flat[base_t + i] (zero on padded border).
    // float4 granules never cross a p boundary (t%4==0, 4|64). 1089 float4s.
    #pragma unroll 1
    for (unsigned q = tid; q < NP / 4; q += 384) {
        unsigned t  = base_t + 4u * q;
        unsigned p  = t >> 6;
        unsigned c  = t & 63u;
        unsigned rp = (p * 993u) >> 16;    // == p/66 for p < 4356 (exact)
        unsigned cp = p - 66u * rp;
        float4 v = make_float4(0.f, 0.f, 0.f, 0.f);
        if ((rp - 1u) < 64u && (cp - 1u) < 64u) {
            v = __ldcs(reinterpret_cast<const float4*>(
                    inb + ((p - 2u * rp - 65u) << 6) + c));   // read-once
        }
        reinterpret_cast<float4*>(smem.win)[q] = v;
    }
    __syncthreads();

    // ---- Store phase: 12 chunks of 16 rows, double-buffered TMA pipeline.
    const int s0 = 4 * tx;
    const int jp0 =  s0      / 3 +  s0      % 3;
    const int jp1 = (s0 + 1) / 3 + (s0 + 1) % 3;
    const int jp2 = (s0 + 2) / 3 + (s0 + 2) % 3;
    const int jp3 = (s0 + 3) / 3 + (s0 + 3) % 3;

    const uint32_t buf_a0 = (uint32_t)__cvta_generic_to_shared(smem.buf[0]);
    const uint32_t buf_a1 = (uint32_t)__cvta_generic_to_shared(smem.buf[1]);
    float* __restrict__ outtile = out + (size_t)(b * 64 + c2) * (OUT * OUT);

    #pragma unroll 1
    for (int c = 0; c < NCHUNK; ++c) {
        if (c >= 2) {
            // buffer (c&1) reused: its TMA (chunk c-2) must be done.
            if (tid == 0)
                asm volatile("cp.async.bulk.wait_group.read 1;" ::: "memory");
            __syncthreads();
        }
        float* buf = smem.buf[c & 1];

        // fill: each thread writes rows ty and ty+8 of this 16-row chunk
        #pragma unroll
        for (int k = 0; k < 2; ++k) {
            const int rl = ty + 8 * k;                 // 0..15
            const int rg = c * CHUNK_ROWS + rl;        // global output row
            const int ip = rg / 3 + rg % 3;
            const float* row = smem.win + ip * HP;
            float4 v = make_float4(row[jp0], row[jp1], row[jp2], row[jp3]);
            *reinterpret_cast<float4*>(buf + rl * OUT + s0) = v;
        }
        __syncthreads();

        if (tid == 0) {
            asm volatile("fence.proxy.async.shared::cta;" ::: "memory");
            asm volatile(
                "cp.async.bulk.global.shared::cta.bulk_group [%0], [%1], %2;"
                :: "l"(outtile + (size_t)c * CHUNK_FLTS),
                   "r"((c & 1) ? buf_a1 : buf_a0),
                   "r"((unsigned)CHUNK_BYTES)
                : "memory");
            asm volatile("cp.async.bulk.commit_group;" ::: "memory");
        }
    }
    // drain all pending bulk stores before block exit
    if (tid == 0)
        asm volatile("cp.async.bulk.wait_group.read 0;" ::: "memory");
}

extern "C" void kernel_launch(void* const* d_in, const int* in_sizes, int n_in,
                              void* d_out, int out_size) {
    const float* in  = (const float*)d_in[0];
    float*       out = (float*)d_out;
    (void)in_sizes; (void)n_in; (void)out_size;

    dim3 grid(64, 32);        // (c2, b)
    dim3 block(48, 8);        // 384 threads
    padding_jacobians_kernel<<<grid, block>>>(in, out);
}